// round 13
// baseline (speedup 1.0000x reference)
#include <cuda_runtime.h>
#include <cuda_bf16.h>
#include <cstdint>

// ---------------- problem constants ----------------
#define MAXN 50000

// ---------------- device scratch ----------------
__device__ float g_sums[MAXN * 256];
__device__ int   g_cnt [MAXN];
__device__ int   g_idx64;
// weight blobs: subchunk = one k16 slice, [n (256)][stride 48 B], hi then lo
#define SUB_BYTES 12288
__device__ __align__(16) unsigned char g_w1blob[32 * SUB_BYTES];   // w1a (K=256)
__device__ __align__(16) unsigned char g_w2blob[32 * SUB_BYTES];   // w1b (K=256)
__device__ __align__(16) unsigned char g_wnablob[48 * SUB_BYTES];  // w2a (K=384)
__device__ __align__(16) unsigned char g_wnbblob[32 * SUB_BYTES];  // w2b (K=256)

// ---------------- edge smem layout (bytes): 128-edge tile ----------------
#define A_STRIDE_B 528              // 264 halves per row (256 + 8 pad)
#define SA_HI  0                    // 128*528 = 67584
#define SA_LO  67584
#define SB0    135168
#define SB1    147456
#define SBIA   159744               // b1a 256 floats
#define SBIB   160768               // b1b 256 floats
#define SROW   161792               // 128 ints
#define SCOL   162304
#define EDGE_SMEM 162816

// ---------------- node smem layout (bytes) ----------------
#define NA_STRIDE_B 784             // 392 halves per row (384 + 8 pad)
#define NA_HI  0
#define NA_LO  50176
#define NB0    100352
#define NB1    112640
#define NB2A   124928
#define NB2B   125952
#define NSINV  126976
#define NODE_SMEM 127232

// ---------------- helpers ----------------
__device__ __forceinline__ uint32_t smem_u32(const void* p) {
    uint32_t a;
    asm("{ .reg .u64 t; cvta.to.shared.u64 t, %1; cvt.u32.u64 %0, t; }" : "=r"(a) : "l"(p));
    return a;
}
__device__ __forceinline__ void cp16(uint32_t saddr, const void* gaddr) {
    asm volatile("cp.async.cg.shared.global [%0], [%1], 16;" :: "r"(saddr), "l"(gaddr));
}
#define CP_COMMIT() asm volatile("cp.async.commit_group;")
#define CP_WAIT1()  asm volatile("cp.async.wait_group 1;")

__device__ __forceinline__ void red_add_v2(float* p, float a, float b) {
    asm volatile("red.global.add.v2.f32 [%0], {%1, %2};" :: "l"(p), "f"(a), "f"(b) : "memory");
}
__device__ __forceinline__ void mma16816(float* c, const uint32_t* a, const uint32_t* b) {
    asm volatile(
        "mma.sync.aligned.m16n8k16.row.col.f32.bf16.bf16.f32 "
        "{%0,%1,%2,%3}, {%4,%5,%6,%7}, {%8,%9}, {%0,%1,%2,%3};"
        : "+f"(c[0]), "+f"(c[1]), "+f"(c[2]), "+f"(c[3])
        : "r"(a[0]), "r"(a[1]), "r"(a[2]), "r"(a[3]), "r"(b[0]), "r"(b[1]));
}
__device__ __forceinline__ void ldm_x4(uint32_t addr, uint32_t* r) {
    asm volatile("ldmatrix.sync.aligned.m8n8.x4.shared.b16 {%0,%1,%2,%3}, [%4];"
                 : "=r"(r[0]), "=r"(r[1]), "=r"(r[2]), "=r"(r[3]) : "r"(addr));
}
__device__ __forceinline__ void split2(float v0, float v1, uint32_t& hi, uint32_t& lo) {
    __nv_bfloat16 h0 = __float2bfloat16(v0), h1 = __float2bfloat16(v1);
    __nv_bfloat162 hh{h0, h1};
    __nv_bfloat162 ll{__float2bfloat16(v0 - __bfloat162float(h0)),
                      __float2bfloat16(v1 - __bfloat162float(h1))};
    hi = *(uint32_t*)&hh;
    lo = *(uint32_t*)&ll;
}

// ======================================================================
// zero + detect combined (single launch -> edge kernel is launch #6)
// ======================================================================
__global__ void zero_detect_kernel(const int* __restrict__ ei_raw, int n_nodes) {
    int tid = blockIdx.x * blockDim.x + threadIdx.x;
    int stride = gridDim.x * blockDim.x;
    int tot4 = n_nodes * 64;
    float4* s4 = (float4*)g_sums;
    float4 z = make_float4(0.f, 0.f, 0.f, 0.f);
    for (int i = tid; i < tot4; i += stride) s4[i] = z;
    for (int i = tid; i < n_nodes; i += stride) g_cnt[i] = 0;
    if (blockIdx.x == 0) {
        __shared__ int any_nonzero;
        if (threadIdx.x == 0) any_nonzero = 0;
        __syncthreads();
        for (int i = threadIdx.x; i < 1024; i += blockDim.x)
            if (ei_raw[2 * i + 1] != 0) any_nonzero = 1;
        __syncthreads();
        if (threadIdx.x == 0) g_idx64 = (any_nonzero == 0) ? 1 : 0;
    }
}
__device__ __forceinline__ int load_idx(const void* ei, long long pos, int nmax) {
    int v = g_idx64 ? (int)((const long long*)ei)[pos] : ((const int*)ei)[pos];
    return min(max(v, 0), nmax - 1);
}

// ======================================================================
// prep: w [K][256 N] fp32 -> subchunks (B^T, 48B padded rows)
// ======================================================================
__global__ void prep_weights_kernel(const float* __restrict__ w, unsigned char* __restrict__ blob, int K) {
    int idx = blockIdx.x * blockDim.x + threadIdx.x;
    if (idx >= K * 256) return;
    int k = idx >> 8, n = idx & 255;
    float v = w[idx];
    __nv_bfloat16 hi = __float2bfloat16(v);
    __nv_bfloat16 lo = __float2bfloat16(v - __bfloat162float(hi));
    unsigned char* base = blob + (uint32_t)(k >> 4) * (2 * SUB_BYTES) + n * 48 + (k & 15) * 2;
    *(__nv_bfloat16*)(base)             = hi;
    *(__nv_bfloat16*)(base + SUB_BYTES) = lo;
}

// ---- shared GEMM machinery macros ----
#define A_LOAD(SAHI, SALO, STRIDE, C)                                  \
    _Pragma("unroll")                                                  \
    for (int mt = 0; mt < 2; mt++) {                                   \
        uint32_t row = (uint32_t)(mb + mt * 16 + ((sel & 1) << 3) + rin); \
        uint32_t byt = row * (STRIDE) + (uint32_t)(C) * 32 + ((sel >> 1) << 4); \
        ldm_x4(sbase + (SAHI) + byt, ahi[mt]);                         \
        ldm_x4(sbase + (SALO) + byt, alo[mt]);                         \
    }

#define B_PASS(SBCUR, NTERMS)                                          \
    _Pragma("unroll")                                                  \
    for (int j = 0; j < 8; j += 2) {                                   \
        uint32_t n = (uint32_t)(nb + (j + (sel >> 1)) * 8 + rin);      \
        uint32_t byt = n * 48u + ((uint32_t)(sel & 1) << 4);           \
        uint32_t b[4];                                                 \
        ldm_x4(sbase + (SBCUR) + byt, b);                              \
        _Pragma("unroll")                                              \
        for (int mt = 0; mt < 2; mt++) {                               \
            mma16816(acc[mt][j],     ahi[mt], b);                      \
            mma16816(acc[mt][j + 1], ahi[mt], b + 2);                  \
            if (NTERMS == 2) {                                         \
                mma16816(acc[mt][j],     alo[mt], b);                  \
                mma16816(acc[mt][j + 1], alo[mt], b + 2);              \
            }                                                          \
        }                                                              \
    }

// ======================================================================
// edge kernel: HMMA bf16-3split, 128 edges / CTA, 512 threads (16 warps)
// ======================================================================
__global__ __launch_bounds__(512, 1)
void edge_mma_kernel(const float* __restrict__ x,
                     const void* __restrict__ edge_index,
                     const float* __restrict__ edge_attr,
                     const float* __restrict__ b1a, const float* __restrict__ b1b,
                     int E, int N)
{
    extern __shared__ __align__(16) unsigned char smem[];
    const uint32_t sbase = smem_u32(smem);
    const int tid  = threadIdx.x;
    const int lane = tid & 31;
    const int w    = tid >> 5;          // 16 warps
    const int g    = lane >> 2;
    const int tg   = lane & 3;
    const int mb   = (w >> 2) * 32;     // 0/32/64/96
    const int nb   = (w & 3) * 64;      // 0/64/128/192
    const int sel  = lane >> 3;
    const int rin  = lane & 7;

    const int e0 = blockIdx.x * 128;
    const int ecnt = min(128, E - e0);
    int*   srow = (int*)(smem + SROW);
    int*   scol = (int*)(smem + SCOL);
    float* sba  = (float*)(smem + SBIA);
    float* sbb  = (float*)(smem + SBIB);

    if (tid < 128) {
        int r = -1, c = -1;
        if (tid < ecnt) {
            r = load_idx(edge_index, (long long)(e0 + tid), N);
            c = load_idx(edge_index, (long long)E + e0 + tid, N);
            atomicAdd(&g_cnt[c], 1);
        }
        srow[tid] = r;
        scol[tid] = c;
    }
    if (tid < 256) {
        sba[tid] = b1a[tid];
        sbb[tid] = b1b[tid];
    }
    __syncthreads();

    // ---- gather inputs, split, store to A_hi/A_lo ----
    for (int idx = tid; idx < 128 * 32; idx += 512) {       // x : k = c4*4
        int e = idx >> 5, c4 = idx & 31;
        float4 v = make_float4(0.f, 0.f, 0.f, 0.f);
        if (e < ecnt) v = *(const float4*)(x + (long long)srow[e] * 128 + c4 * 4);
        uint32_t h0, l0, h1, l1;
        split2(v.x, v.y, h0, l0);
        split2(v.z, v.w, h1, l1);
        uint32_t off = (uint32_t)e * A_STRIDE_B + (uint32_t)c4 * 8;
        *(uint2*)(smem + SA_HI + off) = make_uint2(h0, h1);
        *(uint2*)(smem + SA_LO + off) = make_uint2(l0, l1);
    }
    for (int idx = tid; idx < 128 * 32; idx += 512) {       // edge_attr : k = 128 + c4*4
        int e = idx >> 5, c4 = idx & 31;
        float4 v = make_float4(0.f, 0.f, 0.f, 0.f);
        if (e < ecnt) v = *(const float4*)(edge_attr + (long long)(e0 + e) * 128 + c4 * 4);
        uint32_t h0, l0, h1, l1;
        split2(v.x, v.y, h0, l0);
        split2(v.z, v.w, h1, l1);
        uint32_t off = (uint32_t)e * A_STRIDE_B + 256u + (uint32_t)c4 * 8;
        *(uint2*)(smem + SA_HI + off) = make_uint2(h0, h1);
        *(uint2*)(smem + SA_LO + off) = make_uint2(l0, l1);
    }
    __syncthreads();

    float acc[2][8][4];
    #pragma unroll
    for (int mt = 0; mt < 2; mt++)
        #pragma unroll
        for (int nt = 0; nt < 8; nt++)
            #pragma unroll
            for (int i = 0; i < 4; i++) acc[mt][nt][i] = 0.f;

    uint32_t ahi[2][4], alo[2][4];

    // subchunk copy: 768 x 16B with 512 threads
    #define CP_SUB_E(GSRC, SDST)                                           \
        {                                                                  \
            const unsigned char* _g = (GSRC);                              \
            uint32_t _s = sbase + (SDST);                                  \
            cp16(_s + tid * 16, _g + tid * 16);                            \
            if (tid < 256) cp16(_s + (tid + 512) * 16, _g + (tid + 512) * 16); \
        }

    // ---- GEMM1 ----
    CP_SUB_E(g_w1blob, SB0);
    CP_COMMIT();
    for (int s = 0; s < 32; s++) {
        if (s < 31) { CP_SUB_E(g_w1blob + (s + 1) * SUB_BYTES, ((s + 1) & 1) ? SB1 : SB0); }
        else        { CP_SUB_E(g_w2blob, SB0); }
        CP_COMMIT();
        CP_WAIT1();
        __syncthreads();
        uint32_t sb = (s & 1) ? SB1 : SB0;
        if (!(s & 1)) { A_LOAD(SA_HI, SA_LO, A_STRIDE_B, s >> 1); B_PASS(sb, 2); }
        else          { B_PASS(sb, 1); }
        __syncthreads();
    }

    // ---- layer-1 epilogue: bias + ELU + re-split -> overwrite A ----
    {
        #pragma unroll
        for (int mt = 0; mt < 2; mt++) {
            uint32_t r0 = (uint32_t)(mb + mt * 16 + g);
            #pragma unroll
            for (int nt = 0; nt < 8; nt++) {
                int cb = nb + nt * 8 + tg * 2;
                float b0 = sba[cb], b1 = sba[cb + 1];
                float v00 = acc[mt][nt][0] + b0, v01 = acc[mt][nt][1] + b1;
                float v10 = acc[mt][nt][2] + b0, v11 = acc[mt][nt][3] + b1;
                v00 = (v00 > 0.f) ? v00 : expm1f(v00);
                v01 = (v01 > 0.f) ? v01 : expm1f(v01);
                v10 = (v10 > 0.f) ? v10 : expm1f(v10);
                v11 = (v11 > 0.f) ? v11 : expm1f(v11);
                uint32_t hi, lo;
                uint32_t o = r0 * A_STRIDE_B + (uint32_t)cb * 2;
                split2(v00, v01, hi, lo);
                *(uint32_t*)(smem + SA_HI + o) = hi;
                *(uint32_t*)(smem + SA_LO + o) = lo;
                o += 8 * A_STRIDE_B;
                split2(v10, v11, hi, lo);
                *(uint32_t*)(smem + SA_HI + o) = hi;
                *(uint32_t*)(smem + SA_LO + o) = lo;
                acc[mt][nt][0] = 0.f; acc[mt][nt][1] = 0.f;
                acc[mt][nt][2] = 0.f; acc[mt][nt][3] = 0.f;
            }
        }
    }
    __syncthreads();

    // ---- GEMM2 ----
    for (int s = 0; s < 32; s++) {
        if (s < 31) { CP_SUB_E(g_w2blob + (s + 1) * SUB_BYTES, ((s + 1) & 1) ? SB1 : SB0); }
        CP_COMMIT();
        CP_WAIT1();
        __syncthreads();
        uint32_t sb = (s & 1) ? SB1 : SB0;
        if (!(s & 1)) { A_LOAD(SA_HI, SA_LO, A_STRIDE_B, s >> 1); B_PASS(sb, 2); }
        else          { B_PASS(sb, 1); }
        __syncthreads();
    }

    // ---- scatter epilogue ----
    {
        #pragma unroll
        for (int mt = 0; mt < 2; mt++) {
            int er0 = mb + mt * 16 + g;
            int c0 = scol[er0];
            int c1 = scol[er0 + 8];
            float* p0 = (c0 >= 0) ? (g_sums + (long long)c0 * 256) : nullptr;
            float* p1 = (c1 >= 0) ? (g_sums + (long long)c1 * 256) : nullptr;
            #pragma unroll
            for (int nt = 0; nt < 8; nt++) {
                int cb = nb + nt * 8 + tg * 2;
                float b0 = sbb[cb], b1 = sbb[cb + 1];
                if (p0) red_add_v2(p0 + cb, acc[mt][nt][0] + b0, acc[mt][nt][1] + b1);
                if (p1) red_add_v2(p1 + cb, acc[mt][nt][2] + b0, acc[mt][nt][3] + b1);
            }
        }
    }
}

// ======================================================================
// node kernel: HMMA bf16-3split, 64 nodes / CTA, 256 threads
// ======================================================================
__global__ __launch_bounds__(256, 1)
void node_mma_kernel(const float* __restrict__ x,
                     const float* __restrict__ b2a, const float* __restrict__ b2b,
                     float* __restrict__ out, int N)
{
    extern __shared__ __align__(16) unsigned char smem[];
    const uint32_t sbase = smem_u32(smem);
    const int tid  = threadIdx.x;
    const int lane = tid & 31;
    const int w    = tid >> 5;
    const int g    = lane >> 2;
    const int tg   = lane & 3;
    const int mb   = (w >> 2) * 32;
    const int nb   = (w & 3) * 64;
    const int sel  = lane >> 3;
    const int rin  = lane & 7;

    const int n0 = blockIdx.x * 64;
    const int ncnt = min(64, N - n0);
    float* sba  = (float*)(smem + NB2A);
    float* sbb  = (float*)(smem + NB2B);
    float* sinv = (float*)(smem + NSINV);

    if (tid < 64) {
        float inv = 0.f;
        if (tid < ncnt) inv = 1.0f / (float)max(g_cnt[n0 + tid], 1);
        sinv[tid] = inv;
    }
    if (tid < 256) {
        sba[tid] = b2a[tid];
        sbb[tid] = b2b[tid];
    }
    __syncthreads();

    for (int idx = tid; idx < 64 * 32; idx += 256) {
        int e = idx >> 5, c4 = idx & 31;
        float4 v = make_float4(0.f, 0.f, 0.f, 0.f);
        if (e < ncnt) v = *(const float4*)(x + (long long)(n0 + e) * 128 + c4 * 4);
        uint32_t h0, l0, h1, l1;
        split2(v.x, v.y, h0, l0);
        split2(v.z, v.w, h1, l1);
        uint32_t off = (uint32_t)e * NA_STRIDE_B + (uint32_t)c4 * 8;
        *(uint2*)(smem + NA_HI + off) = make_uint2(h0, h1);
        *(uint2*)(smem + NA_LO + off) = make_uint2(l0, l1);
    }
    for (int idx = tid; idx < 64 * 64; idx += 256) {
        int e = idx >> 6, c4 = idx & 63;
        float4 v = make_float4(0.f, 0.f, 0.f, 0.f);
        if (e < ncnt) {
            v = *(const float4*)(g_sums + (long long)(n0 + e) * 256 + c4 * 4);
            float inv = sinv[e];
            v.x *= inv; v.y *= inv; v.z *= inv; v.w *= inv;
        }
        uint32_t h0, l0, h1, l1;
        split2(v.x, v.y, h0, l0);
        split2(v.z, v.w, h1, l1);
        uint32_t off = (uint32_t)e * NA_STRIDE_B + 256u + (uint32_t)c4 * 8;
        *(uint2*)(smem + NA_HI + off) = make_uint2(h0, h1);
        *(uint2*)(smem + NA_LO + off) = make_uint2(l0, l1);
    }
    __syncthreads();

    float acc[2][8][4];
    #pragma unroll
    for (int mt = 0; mt < 2; mt++)
        #pragma unroll
        for (int nt = 0; nt < 8; nt++)
            #pragma unroll
            for (int i = 0; i < 4; i++) acc[mt][nt][i] = 0.f;

    uint32_t ahi[2][4], alo[2][4];

    #define CP_SUB_N(GSRC, SDST)                                           \
        {                                                                  \
            const unsigned char* _g = (GSRC);                              \
            uint32_t _s = sbase + (SDST);                                  \
            _Pragma("unroll")                                              \
            for (int _j = 0; _j < 3; _j++)                                 \
                cp16(_s + (tid + _j * 256) * 16, _g + (tid + _j * 256) * 16); \
        }

    // ---- GEMM1: K=384 -> 48 subchunks ----
    CP_SUB_N(g_wnablob, NB0);
    CP_COMMIT();
    for (int s = 0; s < 48; s++) {
        if (s < 47) { CP_SUB_N(g_wnablob + (s + 1) * SUB_BYTES, ((s + 1) & 1) ? NB1 : NB0); }
        else        { CP_SUB_N(g_wnbblob, NB0); }
        CP_COMMIT();
        CP_WAIT1();
        __syncthreads();
        uint32_t sb = (s & 1) ? NB1 : NB0;
        if (!(s & 1)) { A_LOAD(NA_HI, NA_LO, NA_STRIDE_B, s >> 1); B_PASS(sb, 2); }
        else          { B_PASS(sb, 1); }
        __syncthreads();
    }

    // ---- layer epilogue ----
    {
        #pragma unroll
        for (int mt = 0; mt < 2; mt++) {
            uint32_t r0 = (uint32_t)(mb + mt * 16 + g);
            #pragma unroll
            for (int nt = 0; nt < 8; nt++) {
                int cb = nb + nt * 8 + tg * 2;
                float b0 = sba[cb], b1 = sba[cb + 1];
                float v00 = acc[mt][nt][0] + b0, v01 = acc[mt][nt][1] + b1;
                float v10 = acc[mt][nt][2] + b0, v11 = acc[mt][nt][3] + b1;
                v00 = (v00 > 0.f) ? v00 : expm1f(v00);
                v01 = (v01 > 0.f) ? v01 : expm1f(v01);
                v10 = (v10 > 0.f) ? v10 : expm1f(v10);
                v11 = (v11 > 0.f) ? v11 : expm1f(v11);
                uint32_t hi, lo;
                uint32_t o = r0 * NA_STRIDE_B + (uint32_t)cb * 2;
                split2(v00, v01, hi, lo);
                *(uint32_t*)(smem + NA_HI + o) = hi;
                *(uint32_t*)(smem + NA_LO + o) = lo;
                o += 8 * NA_STRIDE_B;
                split2(v10, v11, hi, lo);
                *(uint32_t*)(smem + NA_HI + o) = hi;
                *(uint32_t*)(smem + NA_LO + o) = lo;
                acc[mt][nt][0] = 0.f; acc[mt][nt][1] = 0.f;
                acc[mt][nt][2] = 0.f; acc[mt][nt][3] = 0.f;
            }
        }
    }
    __syncthreads();

    // ---- GEMM2: K=256 -> 32 subchunks ----
    for (int s = 0; s < 32; s++) {
        if (s < 31) { CP_SUB_N(g_wnbblob + (s + 1) * SUB_BYTES, ((s + 1) & 1) ? NB1 : NB0); }
        CP_COMMIT();
        CP_WAIT1();
        __syncthreads();
        uint32_t sb = (s & 1) ? NB1 : NB0;
        if (!(s & 1)) { A_LOAD(NA_HI, NA_LO, NA_STRIDE_B, s >> 1); B_PASS(sb, 2); }
        else          { B_PASS(sb, 1); }
        __syncthreads();
    }

    // ---- final epilogue: + b2b -> out ----
    {
        #pragma unroll
        for (int mt = 0; mt < 2; mt++) {
            int r0 = mb + mt * 16 + g;
            int nrow0 = n0 + r0, nrow1 = n0 + r0 + 8;
            #pragma unroll
            for (int nt = 0; nt < 8; nt++) {
                int cb = nb + nt * 8 + tg * 2;
                float b0 = sbb[cb], b1 = sbb[cb + 1];
                if (r0 < ncnt)
                    *(float2*)(out + (long long)nrow0 * 256 + cb) =
                        make_float2(acc[mt][nt][0] + b0, acc[mt][nt][1] + b1);
                if (r0 + 8 < ncnt)
                    *(float2*)(out + (long long)nrow1 * 256 + cb) =
                        make_float2(acc[mt][nt][2] + b0, acc[mt][nt][3] + b1);
            }
        }
    }
}

// ======================================================================
// launch   (order: zero_detect, prep x4, edge <- ncu captures #6, node)
// ======================================================================
extern "C" void kernel_launch(void* const* d_in, const int* in_sizes, int n_in,
                              void* d_out, int out_size)
{
    const float* x  = (const float*)d_in[0];
    const void*  ei = d_in[1];
    const float* ea = (const float*)d_in[2];
    const float* w1a = (const float*)d_in[5];
    const float* b1a = (const float*)d_in[6];
    const float* w1b = (const float*)d_in[7];
    const float* b1b = (const float*)d_in[8];
    const float* w2a = (const float*)d_in[9];
    const float* b2a = (const float*)d_in[10];
    const float* w2b = (const float*)d_in[11];
    const float* b2b = (const float*)d_in[12];
    float* out = (float*)d_out;

    const int N = in_sizes[0] / 128;
    const int E = in_sizes[1] / 2;

    unsigned char *w1blob = nullptr, *w2blob = nullptr, *wnablob = nullptr, *wnbblob = nullptr;
    cudaGetSymbolAddress((void**)&w1blob, g_w1blob);
    cudaGetSymbolAddress((void**)&w2blob, g_w2blob);
    cudaGetSymbolAddress((void**)&wnablob, g_wnablob);
    cudaGetSymbolAddress((void**)&wnbblob, g_wnbblob);

    cudaFuncSetAttribute(edge_mma_kernel, cudaFuncAttributeMaxDynamicSharedMemorySize, EDGE_SMEM);
    cudaFuncSetAttribute(node_mma_kernel, cudaFuncAttributeMaxDynamicSharedMemorySize, NODE_SMEM);

    zero_detect_kernel<<<1024, 256>>>((const int*)ei, N);
    prep_weights_kernel<<<128, 512>>>(w1a, w1blob, 256);
    prep_weights_kernel<<<128, 512>>>(w1b, w2blob, 256);
    prep_weights_kernel<<<192, 512>>>(w2a, wnablob, 384);
    prep_weights_kernel<<<128, 512>>>(w2b, wnbblob, 256);
    edge_mma_kernel<<<(E + 127) / 128, 512, EDGE_SMEM>>>(x, ei, ea, b1a, b1b, E, N);
    node_mma_kernel<<<(N + 63) / 64, 256, NODE_SMEM>>>(x, b2a, b2b, out, N);
}

// round 14
// speedup vs baseline: 1.0898x; 1.0898x over previous
#include <cuda_runtime.h>
#include <cuda_bf16.h>
#include <cstdint>

// ---------------- problem constants ----------------
#define MAXN 50000

// ---------------- device scratch ----------------
__device__ float g_sums[MAXN * 256];
__device__ int   g_cnt [MAXN];
__device__ int   g_idx64;
// weight blobs: subchunk = one k16 slice, [n (256)][stride 48 B], hi then lo
#define SUB_BYTES 12288
__device__ __align__(16) unsigned char g_w1blob[32 * SUB_BYTES];   // w1a (K=256)
__device__ __align__(16) unsigned char g_w2blob[32 * SUB_BYTES];   // w1b (K=256)
__device__ __align__(16) unsigned char g_wnablob[48 * SUB_BYTES];  // w2a (K=384)
__device__ __align__(16) unsigned char g_wnbblob[32 * SUB_BYTES];  // w2b (K=256)

// ---------------- edge smem layout (bytes): 64-edge tile, 3 B-buffers ----
#define A_STRIDE_B 528              // 264 halves per row (256 + 8 pad)
#define SA_HI  0                    // 64*528 = 33792
#define SA_LO  33792
#define SBUF0  67584                // 3 x 12288 ring
#define SBIA   104448               // b1a 256 floats
#define SBIB   105472               // b1b 256 floats
#define SROW   106496               // 64 ints
#define SCOL   106752
#define EDGE_SMEM 107008

// ---------------- node smem layout (bytes) ----------------
#define NA_STRIDE_B 784             // 392 halves per row (384 + 8 pad)
#define NA_HI  0
#define NA_LO  50176
#define NB0    100352
#define NB1    112640
#define NB2A   124928
#define NB2B   125952
#define NSINV  126976
#define NODE_SMEM 127232

// ---------------- helpers ----------------
__device__ __forceinline__ uint32_t smem_u32(const void* p) {
    uint32_t a;
    asm("{ .reg .u64 t; cvta.to.shared.u64 t, %1; cvt.u32.u64 %0, t; }" : "=r"(a) : "l"(p));
    return a;
}
__device__ __forceinline__ void cp16(uint32_t saddr, const void* gaddr) {
    asm volatile("cp.async.cg.shared.global [%0], [%1], 16;" :: "r"(saddr), "l"(gaddr));
}
#define CP_COMMIT() asm volatile("cp.async.commit_group;")
#define CP_WAIT1()  asm volatile("cp.async.wait_group 1;")

__device__ __forceinline__ void red_add_v2(float* p, float a, float b) {
    asm volatile("red.global.add.v2.f32 [%0], {%1, %2};" :: "l"(p), "f"(a), "f"(b) : "memory");
}
__device__ __forceinline__ void mma16816(float* c, const uint32_t* a, const uint32_t* b) {
    asm volatile(
        "mma.sync.aligned.m16n8k16.row.col.f32.bf16.bf16.f32 "
        "{%0,%1,%2,%3}, {%4,%5,%6,%7}, {%8,%9}, {%0,%1,%2,%3};"
        : "+f"(c[0]), "+f"(c[1]), "+f"(c[2]), "+f"(c[3])
        : "r"(a[0]), "r"(a[1]), "r"(a[2]), "r"(a[3]), "r"(b[0]), "r"(b[1]));
}
__device__ __forceinline__ void ldm_x4(uint32_t addr, uint32_t* r) {
    asm volatile("ldmatrix.sync.aligned.m8n8.x4.shared.b16 {%0,%1,%2,%3}, [%4];"
                 : "=r"(r[0]), "=r"(r[1]), "=r"(r[2]), "=r"(r[3]) : "r"(addr));
}
__device__ __forceinline__ void split2(float v0, float v1, uint32_t& hi, uint32_t& lo) {
    __nv_bfloat16 h0 = __float2bfloat16(v0), h1 = __float2bfloat16(v1);
    __nv_bfloat162 hh{h0, h1};
    __nv_bfloat162 ll{__float2bfloat16(v0 - __bfloat162float(h0)),
                      __float2bfloat16(v1 - __bfloat162float(h1))};
    hi = *(uint32_t*)&hh;
    lo = *(uint32_t*)&ll;
}

// ======================================================================
// zero + detect combined (keeps edge kernel at launch #6 for ncu)
// ======================================================================
__global__ void zero_detect_kernel(const int* __restrict__ ei_raw, int n_nodes) {
    int tid = blockIdx.x * blockDim.x + threadIdx.x;
    int stride = gridDim.x * blockDim.x;
    int tot4 = n_nodes * 64;
    float4* s4 = (float4*)g_sums;
    float4 z = make_float4(0.f, 0.f, 0.f, 0.f);
    for (int i = tid; i < tot4; i += stride) s4[i] = z;
    for (int i = tid; i < n_nodes; i += stride) g_cnt[i] = 0;
    if (blockIdx.x == 0) {
        __shared__ int any_nonzero;
        if (threadIdx.x == 0) any_nonzero = 0;
        __syncthreads();
        for (int i = threadIdx.x; i < 1024; i += blockDim.x)
            if (ei_raw[2 * i + 1] != 0) any_nonzero = 1;
        __syncthreads();
        if (threadIdx.x == 0) g_idx64 = (any_nonzero == 0) ? 1 : 0;
    }
}
__device__ __forceinline__ int load_idx(const void* ei, long long pos, int nmax) {
    int v = g_idx64 ? (int)((const long long*)ei)[pos] : ((const int*)ei)[pos];
    return min(max(v, 0), nmax - 1);
}

// ======================================================================
// prep: w [K][256 N] fp32 -> subchunks (B^T, 48B padded rows)
// ======================================================================
__global__ void prep_weights_kernel(const float* __restrict__ w, unsigned char* __restrict__ blob, int K) {
    int idx = blockIdx.x * blockDim.x + threadIdx.x;
    if (idx >= K * 256) return;
    int k = idx >> 8, n = idx & 255;
    float v = w[idx];
    __nv_bfloat16 hi = __float2bfloat16(v);
    __nv_bfloat16 lo = __float2bfloat16(v - __bfloat162float(hi));
    unsigned char* base = blob + (uint32_t)(k >> 4) * (2 * SUB_BYTES) + n * 48 + (k & 15) * 2;
    *(__nv_bfloat16*)(base)             = hi;
    *(__nv_bfloat16*)(base + SUB_BYTES) = lo;
}

// ---- shared GEMM machinery macros ----
#define A_LOAD(SAHI, SALO, STRIDE, C)                                  \
    _Pragma("unroll")                                                  \
    for (int mt = 0; mt < 2; mt++) {                                   \
        uint32_t row = (uint32_t)(mb + mt * 16 + ((sel & 1) << 3) + rin); \
        uint32_t byt = row * (STRIDE) + (uint32_t)(C) * 32 + ((sel >> 1) << 4); \
        ldm_x4(sbase + (SAHI) + byt, ahi[mt]);                         \
        ldm_x4(sbase + (SALO) + byt, alo[mt]);                         \
    }

#define B_PASS(SBCUR, NTERMS)                                          \
    _Pragma("unroll")                                                  \
    for (int j = 0; j < 8; j += 2) {                                   \
        uint32_t n = (uint32_t)(nb + (j + (sel >> 1)) * 8 + rin);      \
        uint32_t byt = n * 48u + ((uint32_t)(sel & 1) << 4);           \
        uint32_t b[4];                                                 \
        ldm_x4(sbase + (SBCUR) + byt, b);                              \
        _Pragma("unroll")                                              \
        for (int mt = 0; mt < 2; mt++) {                               \
            mma16816(acc[mt][j],     ahi[mt], b);                      \
            mma16816(acc[mt][j + 1], ahi[mt], b + 2);                  \
            if (NTERMS == 2) {                                         \
                mma16816(acc[mt][j],     alo[mt], b);                  \
                mma16816(acc[mt][j + 1], alo[mt], b + 2);              \
            }                                                          \
        }                                                              \
    }

// ======================================================================
// edge kernel: HMMA bf16-3split, 64 edges / CTA, 256 threads, 2 CTA/SM,
//              triple-buffered single-sync staging ring
// ======================================================================
__global__ __launch_bounds__(256, 2)
void edge_mma_kernel(const float* __restrict__ x,
                     const void* __restrict__ edge_index,
                     const float* __restrict__ edge_attr,
                     const float* __restrict__ b1a, const float* __restrict__ b1b,
                     int E, int N)
{
    extern __shared__ __align__(16) unsigned char smem[];
    const uint32_t sbase = smem_u32(smem);
    const int tid  = threadIdx.x;
    const int lane = tid & 31;
    const int w    = tid >> 5;
    const int g    = lane >> 2;
    const int tg   = lane & 3;
    const int mb   = (w >> 2) * 32;
    const int nb   = (w & 3) * 64;
    const int sel  = lane >> 3;
    const int rin  = lane & 7;

    const int e0 = blockIdx.x * 64;
    const int ecnt = min(64, E - e0);
    int*   srow = (int*)(smem + SROW);
    int*   scol = (int*)(smem + SCOL);
    float* sba  = (float*)(smem + SBIA);
    float* sbb  = (float*)(smem + SBIB);

    if (tid < 64) {
        int r = -1, c = -1;
        if (tid < ecnt) {
            r = load_idx(edge_index, (long long)(e0 + tid), N);
            c = load_idx(edge_index, (long long)E + e0 + tid, N);
            atomicAdd(&g_cnt[c], 1);
        }
        srow[tid] = r;
        scol[tid] = c;
    }
    if (tid < 256) {
        sba[tid] = b1a[tid];
        sbb[tid] = b1b[tid];
    }
    __syncthreads();

    // ---- gather inputs, split, store to A_hi/A_lo ----
    for (int idx = tid; idx < 64 * 32; idx += 256) {
        int e = idx >> 5, c4 = idx & 31;
        float4 v = make_float4(0.f, 0.f, 0.f, 0.f);
        if (e < ecnt) v = *(const float4*)(x + (long long)srow[e] * 128 + c4 * 4);
        uint32_t h0, l0, h1, l1;
        split2(v.x, v.y, h0, l0);
        split2(v.z, v.w, h1, l1);
        uint32_t off = (uint32_t)e * A_STRIDE_B + (uint32_t)c4 * 8;
        *(uint2*)(smem + SA_HI + off) = make_uint2(h0, h1);
        *(uint2*)(smem + SA_LO + off) = make_uint2(l0, l1);
    }
    for (int idx = tid; idx < 64 * 32; idx += 256) {
        int e = idx >> 5, c4 = idx & 31;
        float4 v = make_float4(0.f, 0.f, 0.f, 0.f);
        if (e < ecnt) v = *(const float4*)(edge_attr + (long long)(e0 + e) * 128 + c4 * 4);
        uint32_t h0, l0, h1, l1;
        split2(v.x, v.y, h0, l0);
        split2(v.z, v.w, h1, l1);
        uint32_t off = (uint32_t)e * A_STRIDE_B + 256u + (uint32_t)c4 * 8;
        *(uint2*)(smem + SA_HI + off) = make_uint2(h0, h1);
        *(uint2*)(smem + SA_LO + off) = make_uint2(l0, l1);
    }
    __syncthreads();

    float acc[2][8][4];
    #pragma unroll
    for (int mt = 0; mt < 2; mt++)
        #pragma unroll
        for (int nt = 0; nt < 8; nt++)
            #pragma unroll
            for (int i = 0; i < 4; i++) acc[mt][nt][i] = 0.f;

    uint32_t ahi[2][4], alo[2][4];

    // subchunk source: 0..31 -> w1a, 32..63 -> w1b
    #define SRC(S) ((S) < 32 ? g_w1blob + (S) * SUB_BYTES : g_w2blob + ((S) - 32) * SUB_BYTES)
    // subchunk copy: 768 x 16B with 256 threads (3 each)
    #define CP_SUB(GSRC, SDST)                                             \
        {                                                                  \
            const unsigned char* _g = (GSRC);                              \
            uint32_t _s = sbase + (SDST);                                  \
            _Pragma("unroll")                                              \
            for (int _j = 0; _j < 3; _j++)                                 \
                cp16(_s + (tid + _j * 256) * 16, _g + (tid + _j * 256) * 16); \
        }

    // prologue: prefetch subchunks 0 and 1
    CP_SUB(SRC(0), SBUF0 + 0 * SUB_BYTES);
    CP_COMMIT();
    CP_SUB(SRC(1), SBUF0 + 1 * SUB_BYTES);
    CP_COMMIT();

    // ---- unified mainloop: 64 subchunks, ONE sync per iteration ----
    for (int s = 0; s < 64; s++) {
        CP_WAIT1();                 // group s complete (<=1 outstanding)
        __syncthreads();            // data visible to all; prev readers done
        uint32_t sb = SBUF0 + (uint32_t)(s % 3) * SUB_BYTES;
        int sl = s & 31;            // index within current GEMM
        if (!(sl & 1)) { A_LOAD(SA_HI, SA_LO, A_STRIDE_B, sl >> 1); B_PASS(sb, 2); }
        else           { B_PASS(sb, 1); }

        if (s == 31) {
            // ---- layer-1 epilogue: bias + ELU + re-split -> overwrite A ----
            __syncthreads();        // all GEMM1 A-reads done before rewrite
            #pragma unroll
            for (int mt = 0; mt < 2; mt++) {
                uint32_t r0 = (uint32_t)(mb + mt * 16 + g);
                #pragma unroll
                for (int nt = 0; nt < 8; nt++) {
                    int cb = nb + nt * 8 + tg * 2;
                    float b0 = sba[cb], b1 = sba[cb + 1];
                    float v00 = acc[mt][nt][0] + b0, v01 = acc[mt][nt][1] + b1;
                    float v10 = acc[mt][nt][2] + b0, v11 = acc[mt][nt][3] + b1;
                    v00 = (v00 > 0.f) ? v00 : expm1f(v00);
                    v01 = (v01 > 0.f) ? v01 : expm1f(v01);
                    v10 = (v10 > 0.f) ? v10 : expm1f(v10);
                    v11 = (v11 > 0.f) ? v11 : expm1f(v11);
                    uint32_t hi, lo;
                    uint32_t o = r0 * A_STRIDE_B + (uint32_t)cb * 2;
                    split2(v00, v01, hi, lo);
                    *(uint32_t*)(smem + SA_HI + o) = hi;
                    *(uint32_t*)(smem + SA_LO + o) = lo;
                    o += 8 * A_STRIDE_B;
                    split2(v10, v11, hi, lo);
                    *(uint32_t*)(smem + SA_HI + o) = hi;
                    *(uint32_t*)(smem + SA_LO + o) = lo;
                    acc[mt][nt][0] = 0.f; acc[mt][nt][1] = 0.f;
                    acc[mt][nt][2] = 0.f; acc[mt][nt][3] = 0.f;
                }
            }
            // visibility of new A guaranteed by sync at top of iter 32
        }

        if (s + 2 < 64) { CP_SUB(SRC(s + 2), SBUF0 + (uint32_t)((s + 2) % 3) * SUB_BYTES); }
        CP_COMMIT();                // empty groups keep accounting uniform
    }
    #undef SRC
    #undef CP_SUB

    // ---- scatter epilogue: + b1b, red.global.add.v2 into g_sums ----
    {
        #pragma unroll
        for (int mt = 0; mt < 2; mt++) {
            int er0 = mb + mt * 16 + g;
            int c0 = scol[er0];
            int c1 = scol[er0 + 8];
            float* p0 = (c0 >= 0) ? (g_sums + (long long)c0 * 256) : nullptr;
            float* p1 = (c1 >= 0) ? (g_sums + (long long)c1 * 256) : nullptr;
            #pragma unroll
            for (int nt = 0; nt < 8; nt++) {
                int cb = nb + nt * 8 + tg * 2;
                float b0 = sbb[cb], b1 = sbb[cb + 1];
                if (p0) red_add_v2(p0 + cb, acc[mt][nt][0] + b0, acc[mt][nt][1] + b1);
                if (p1) red_add_v2(p1 + cb, acc[mt][nt][2] + b0, acc[mt][nt][3] + b1);
            }
        }
    }
}

// ======================================================================
// node kernel: HMMA bf16-3split, 64 nodes / CTA, 256 threads (R12)
// ======================================================================
__global__ __launch_bounds__(256, 1)
void node_mma_kernel(const float* __restrict__ x,
                     const float* __restrict__ b2a, const float* __restrict__ b2b,
                     float* __restrict__ out, int N)
{
    extern __shared__ __align__(16) unsigned char smem[];
    const uint32_t sbase = smem_u32(smem);
    const int tid  = threadIdx.x;
    const int lane = tid & 31;
    const int w    = tid >> 5;
    const int g    = lane >> 2;
    const int tg   = lane & 3;
    const int mb   = (w >> 2) * 32;
    const int nb   = (w & 3) * 64;
    const int sel  = lane >> 3;
    const int rin  = lane & 7;

    const int n0 = blockIdx.x * 64;
    const int ncnt = min(64, N - n0);
    float* sba  = (float*)(smem + NB2A);
    float* sbb  = (float*)(smem + NB2B);
    float* sinv = (float*)(smem + NSINV);

    if (tid < 64) {
        float inv = 0.f;
        if (tid < ncnt) inv = 1.0f / (float)max(g_cnt[n0 + tid], 1);
        sinv[tid] = inv;
    }
    if (tid < 256) {
        sba[tid] = b2a[tid];
        sbb[tid] = b2b[tid];
    }
    __syncthreads();

    for (int idx = tid; idx < 64 * 32; idx += 256) {
        int e = idx >> 5, c4 = idx & 31;
        float4 v = make_float4(0.f, 0.f, 0.f, 0.f);
        if (e < ncnt) v = *(const float4*)(x + (long long)(n0 + e) * 128 + c4 * 4);
        uint32_t h0, l0, h1, l1;
        split2(v.x, v.y, h0, l0);
        split2(v.z, v.w, h1, l1);
        uint32_t off = (uint32_t)e * NA_STRIDE_B + (uint32_t)c4 * 8;
        *(uint2*)(smem + NA_HI + off) = make_uint2(h0, h1);
        *(uint2*)(smem + NA_LO + off) = make_uint2(l0, l1);
    }
    for (int idx = tid; idx < 64 * 64; idx += 256) {
        int e = idx >> 6, c4 = idx & 63;
        float4 v = make_float4(0.f, 0.f, 0.f, 0.f);
        if (e < ncnt) {
            v = *(const float4*)(g_sums + (long long)(n0 + e) * 256 + c4 * 4);
            float inv = sinv[e];
            v.x *= inv; v.y *= inv; v.z *= inv; v.w *= inv;
        }
        uint32_t h0, l0, h1, l1;
        split2(v.x, v.y, h0, l0);
        split2(v.z, v.w, h1, l1);
        uint32_t off = (uint32_t)e * NA_STRIDE_B + 256u + (uint32_t)c4 * 8;
        *(uint2*)(smem + NA_HI + off) = make_uint2(h0, h1);
        *(uint2*)(smem + NA_LO + off) = make_uint2(l0, l1);
    }
    __syncthreads();

    float acc[2][8][4];
    #pragma unroll
    for (int mt = 0; mt < 2; mt++)
        #pragma unroll
        for (int nt = 0; nt < 8; nt++)
            #pragma unroll
            for (int i = 0; i < 4; i++) acc[mt][nt][i] = 0.f;

    uint32_t ahi[2][4], alo[2][4];

    #define CP_SUB_N(GSRC, SDST)                                           \
        {                                                                  \
            const unsigned char* _g = (GSRC);                              \
            uint32_t _s = sbase + (SDST);                                  \
            _Pragma("unroll")                                              \
            for (int _j = 0; _j < 3; _j++)                                 \
                cp16(_s + (tid + _j * 256) * 16, _g + (tid + _j * 256) * 16); \
        }

    // ---- GEMM1: K=384 -> 48 subchunks ----
    CP_SUB_N(g_wnablob, NB0);
    CP_COMMIT();
    for (int s = 0; s < 48; s++) {
        if (s < 47) { CP_SUB_N(g_wnablob + (s + 1) * SUB_BYTES, ((s + 1) & 1) ? NB1 : NB0); }
        else        { CP_SUB_N(g_wnbblob, NB0); }
        CP_COMMIT();
        CP_WAIT1();
        __syncthreads();
        uint32_t sb = (s & 1) ? NB1 : NB0;
        if (!(s & 1)) { A_LOAD(NA_HI, NA_LO, NA_STRIDE_B, s >> 1); B_PASS(sb, 2); }
        else          { B_PASS(sb, 1); }
        __syncthreads();
    }

    // ---- layer epilogue ----
    {
        #pragma unroll
        for (int mt = 0; mt < 2; mt++) {
            uint32_t r0 = (uint32_t)(mb + mt * 16 + g);
            #pragma unroll
            for (int nt = 0; nt < 8; nt++) {
                int cb = nb + nt * 8 + tg * 2;
                float b0 = sba[cb], b1 = sba[cb + 1];
                float v00 = acc[mt][nt][0] + b0, v01 = acc[mt][nt][1] + b1;
                float v10 = acc[mt][nt][2] + b0, v11 = acc[mt][nt][3] + b1;
                v00 = (v00 > 0.f) ? v00 : expm1f(v00);
                v01 = (v01 > 0.f) ? v01 : expm1f(v01);
                v10 = (v10 > 0.f) ? v10 : expm1f(v10);
                v11 = (v11 > 0.f) ? v11 : expm1f(v11);
                uint32_t hi, lo;
                uint32_t o = r0 * NA_STRIDE_B + (uint32_t)cb * 2;
                split2(v00, v01, hi, lo);
                *(uint32_t*)(smem + NA_HI + o) = hi;
                *(uint32_t*)(smem + NA_LO + o) = lo;
                o += 8 * NA_STRIDE_B;
                split2(v10, v11, hi, lo);
                *(uint32_t*)(smem + NA_HI + o) = hi;
                *(uint32_t*)(smem + NA_LO + o) = lo;
                acc[mt][nt][0] = 0.f; acc[mt][nt][1] = 0.f;
                acc[mt][nt][2] = 0.f; acc[mt][nt][3] = 0.f;
            }
        }
    }
    __syncthreads();

    // ---- GEMM2: K=256 -> 32 subchunks ----
    for (int s = 0; s < 32; s++) {
        if (s < 31) { CP_SUB_N(g_wnbblob + (s + 1) * SUB_BYTES, ((s + 1) & 1) ? NB1 : NB0); }
        CP_COMMIT();
        CP_WAIT1();
        __syncthreads();
        uint32_t sb = (s & 1) ? NB1 : NB0;
        if (!(s & 1)) { A_LOAD(NA_HI, NA_LO, NA_STRIDE_B, s >> 1); B_PASS(sb, 2); }
        else          { B_PASS(sb, 1); }
        __syncthreads();
    }
    #undef CP_SUB_N

    // ---- final epilogue: + b2b -> out ----
    {
        #pragma unroll
        for (int mt = 0; mt < 2; mt++) {
            int r0 = mb + mt * 16 + g;
            int nrow0 = n0 + r0, nrow1 = n0 + r0 + 8;
            #pragma unroll
            for (int nt = 0; nt < 8; nt++) {
                int cb = nb + nt * 8 + tg * 2;
                float b0 = sbb[cb], b1 = sbb[cb + 1];
                if (r0 < ncnt)
                    *(float2*)(out + (long long)nrow0 * 256 + cb) =
                        make_float2(acc[mt][nt][0] + b0, acc[mt][nt][1] + b1);
                if (r0 + 8 < ncnt)
                    *(float2*)(out + (long long)nrow1 * 256 + cb) =
                        make_float2(acc[mt][nt][2] + b0, acc[mt][nt][3] + b1);
            }
        }
    }
}

// ======================================================================
// launch   (order: zero_detect, prep x4, edge <- ncu #6, node)
// ======================================================================
extern "C" void kernel_launch(void* const* d_in, const int* in_sizes, int n_in,
                              void* d_out, int out_size)
{
    const float* x  = (const float*)d_in[0];
    const void*  ei = d_in[1];
    const float* ea = (const float*)d_in[2];
    const float* w1a = (const float*)d_in[5];
    const float* b1a = (const float*)d_in[6];
    const float* w1b = (const float*)d_in[7];
    const float* b1b = (const float*)d_in[8];
    const float* w2a = (const float*)d_in[9];
    const float* b2a = (const float*)d_in[10];
    const float* w2b = (const float*)d_in[11];
    const float* b2b = (const float*)d_in[12];
    float* out = (float*)d_out;

    const int N = in_sizes[0] / 128;
    const int E = in_sizes[1] / 2;

    unsigned char *w1blob = nullptr, *w2blob = nullptr, *wnablob = nullptr, *wnbblob = nullptr;
    cudaGetSymbolAddress((void**)&w1blob, g_w1blob);
    cudaGetSymbolAddress((void**)&w2blob, g_w2blob);
    cudaGetSymbolAddress((void**)&wnablob, g_wnablob);
    cudaGetSymbolAddress((void**)&wnbblob, g_wnbblob);

    cudaFuncSetAttribute(edge_mma_kernel, cudaFuncAttributeMaxDynamicSharedMemorySize, EDGE_SMEM);
    cudaFuncSetAttribute(node_mma_kernel, cudaFuncAttributeMaxDynamicSharedMemorySize, NODE_SMEM);

    zero_detect_kernel<<<1024, 256>>>((const int*)ei, N);
    prep_weights_kernel<<<128, 512>>>(w1a, w1blob, 256);
    prep_weights_kernel<<<128, 512>>>(w1b, w2blob, 256);
    prep_weights_kernel<<<192, 512>>>(w2a, wnablob, 384);
    prep_weights_kernel<<<128, 512>>>(w2b, wnbblob, 256);
    edge_mma_kernel<<<(E + 63) / 64, 256, EDGE_SMEM>>>(x, ei, ea, b1a, b1b, E, N);
    node_mma_kernel<<<(N + 63) / 64, 256, NODE_SMEM>>>(x, b2a, b2b, out, N);
}

// round 15
// speedup vs baseline: 1.1011x; 1.0104x over previous
#include <cuda_runtime.h>
#include <cuda_bf16.h>
#include <cstdint>

// ---------------- problem constants ----------------
#define MAXN 50000

// ---------------- device scratch ----------------
__device__ float g_sums[MAXN * 256];
__device__ int   g_cnt [MAXN];
__device__ int   g_idx64;
// weight blobs: subchunk = one k16 slice, [n (256)][stride 48 B], hi then lo
#define SUB_BYTES 12288
__device__ __align__(16) unsigned char g_w1blob[32 * SUB_BYTES];   // w1a (K=256)
__device__ __align__(16) unsigned char g_w2blob[32 * SUB_BYTES];   // w1b (K=256)
__device__ __align__(16) unsigned char g_wnablob[48 * SUB_BYTES];  // w2a (K=384)
__device__ __align__(16) unsigned char g_wnbblob[32 * SUB_BYTES];  // w2b (K=256)

// ---------------- edge smem layout (bytes): 64-edge tile, 3-buffer ring --
#define A_STRIDE_B 528              // 264 halves per row (256 + 8 pad)
#define SA_HI  0                    // 64*528 = 33792
#define SA_LO  33792
#define SBUF0  67584                // 3 x 12288 ring
#define SBIA   104448               // b1a 256 floats
#define SBIB   105472               // b1b 256 floats
#define SROW   106496               // 64 ints
#define SCOL   106752
#define EDGE_SMEM 107008

// ---------------- node smem layout (bytes): 3-buffer ring ----------------
#define NA_STRIDE_B 784             // 392 halves per row (384 + 8 pad)
#define NA_HI  0
#define NA_LO  50176
#define NBUF0  100352               // 3 x 12288 ring
#define NB2A   137216
#define NB2B   138240
#define NSINV  139264
#define NODE_SMEM 139520

// ---------------- helpers ----------------
__device__ __forceinline__ uint32_t smem_u32(const void* p) {
    uint32_t a;
    asm("{ .reg .u64 t; cvta.to.shared.u64 t, %1; cvt.u32.u64 %0, t; }" : "=r"(a) : "l"(p));
    return a;
}
__device__ __forceinline__ void cp16(uint32_t saddr, const void* gaddr) {
    asm volatile("cp.async.cg.shared.global [%0], [%1], 16;" :: "r"(saddr), "l"(gaddr));
}
#define CP_COMMIT() asm volatile("cp.async.commit_group;")
#define CP_WAIT1()  asm volatile("cp.async.wait_group 1;")

__device__ __forceinline__ void red_add_v2(float* p, float a, float b) {
    asm volatile("red.global.add.v2.f32 [%0], {%1, %2};" :: "l"(p), "f"(a), "f"(b) : "memory");
}
__device__ __forceinline__ void mma16816(float* c, const uint32_t* a, const uint32_t* b) {
    asm volatile(
        "mma.sync.aligned.m16n8k16.row.col.f32.bf16.bf16.f32 "
        "{%0,%1,%2,%3}, {%4,%5,%6,%7}, {%8,%9}, {%0,%1,%2,%3};"
        : "+f"(c[0]), "+f"(c[1]), "+f"(c[2]), "+f"(c[3])
        : "r"(a[0]), "r"(a[1]), "r"(a[2]), "r"(a[3]), "r"(b[0]), "r"(b[1]));
}
__device__ __forceinline__ void ldm_x4(uint32_t addr, uint32_t* r) {
    asm volatile("ldmatrix.sync.aligned.m8n8.x4.shared.b16 {%0,%1,%2,%3}, [%4];"
                 : "=r"(r[0]), "=r"(r[1]), "=r"(r[2]), "=r"(r[3]) : "r"(addr));
}
__device__ __forceinline__ void split2(float v0, float v1, uint32_t& hi, uint32_t& lo) {
    __nv_bfloat16 h0 = __float2bfloat16(v0), h1 = __float2bfloat16(v1);
    __nv_bfloat162 hh{h0, h1};
    __nv_bfloat162 ll{__float2bfloat16(v0 - __bfloat162float(h0)),
                      __float2bfloat16(v1 - __bfloat162float(h1))};
    hi = *(uint32_t*)&hh;
    lo = *(uint32_t*)&ll;
}

// ======================================================================
// zero + detect combined
// ======================================================================
__global__ void zero_detect_kernel(const int* __restrict__ ei_raw, int n_nodes) {
    int tid = blockIdx.x * blockDim.x + threadIdx.x;
    int stride = gridDim.x * blockDim.x;
    int tot4 = n_nodes * 64;
    float4* s4 = (float4*)g_sums;
    float4 z = make_float4(0.f, 0.f, 0.f, 0.f);
    for (int i = tid; i < tot4; i += stride) s4[i] = z;
    for (int i = tid; i < n_nodes; i += stride) g_cnt[i] = 0;
    if (blockIdx.x == 0) {
        __shared__ int any_nonzero;
        if (threadIdx.x == 0) any_nonzero = 0;
        __syncthreads();
        for (int i = threadIdx.x; i < 1024; i += blockDim.x)
            if (ei_raw[2 * i + 1] != 0) any_nonzero = 1;
        __syncthreads();
        if (threadIdx.x == 0) g_idx64 = (any_nonzero == 0) ? 1 : 0;
    }
}
__device__ __forceinline__ int load_idx(const void* ei, long long pos, int nmax) {
    int v = g_idx64 ? (int)((const long long*)ei)[pos] : ((const int*)ei)[pos];
    return min(max(v, 0), nmax - 1);
}

// ======================================================================
// prep: w [K][256 N] fp32 -> subchunks (B^T, 48B padded rows)
// ======================================================================
__global__ void prep_weights_kernel(const float* __restrict__ w, unsigned char* __restrict__ blob, int K) {
    int idx = blockIdx.x * blockDim.x + threadIdx.x;
    if (idx >= K * 256) return;
    int k = idx >> 8, n = idx & 255;
    float v = w[idx];
    __nv_bfloat16 hi = __float2bfloat16(v);
    __nv_bfloat16 lo = __float2bfloat16(v - __bfloat162float(hi));
    unsigned char* base = blob + (uint32_t)(k >> 4) * (2 * SUB_BYTES) + n * 48 + (k & 15) * 2;
    *(__nv_bfloat16*)(base)             = hi;
    *(__nv_bfloat16*)(base + SUB_BYTES) = lo;
}

// ---- shared GEMM machinery macros ----
#define A_LOAD(SAHI, SALO, STRIDE, C)                                  \
    _Pragma("unroll")                                                  \
    for (int mt = 0; mt < 2; mt++) {                                   \
        uint32_t row = (uint32_t)(mb + mt * 16 + ((sel & 1) << 3) + rin); \
        uint32_t byt = row * (STRIDE) + (uint32_t)(C) * 32 + ((sel >> 1) << 4); \
        ldm_x4(sbase + (SAHI) + byt, ahi[mt]);                         \
        ldm_x4(sbase + (SALO) + byt, alo[mt]);                         \
    }

#define B_PASS(SBCUR, NTERMS)                                          \
    _Pragma("unroll")                                                  \
    for (int j = 0; j < 8; j += 2) {                                   \
        uint32_t n = (uint32_t)(nb + (j + (sel >> 1)) * 8 + rin);      \
        uint32_t byt = n * 48u + ((uint32_t)(sel & 1) << 4);           \
        uint32_t b[4];                                                 \
        ldm_x4(sbase + (SBCUR) + byt, b);                              \
        _Pragma("unroll")                                              \
        for (int mt = 0; mt < 2; mt++) {                               \
            mma16816(acc[mt][j],     ahi[mt], b);                      \
            mma16816(acc[mt][j + 1], ahi[mt], b + 2);                  \
            if (NTERMS == 2) {                                         \
                mma16816(acc[mt][j],     alo[mt], b);                  \
                mma16816(acc[mt][j + 1], alo[mt], b + 2);              \
            }                                                          \
        }                                                              \
    }

// subchunk copy: 768 x 16B with 256 threads (3 each)
#define CP_SUB(GSRC, SDST)                                             \
    {                                                                  \
        const unsigned char* _g = (GSRC);                              \
        uint32_t _s = sbase + (SDST);                                  \
        _Pragma("unroll")                                              \
        for (int _j = 0; _j < 3; _j++)                                 \
            cp16(_s + (tid + _j * 256) * 16, _g + (tid + _j * 256) * 16); \
    }

// ======================================================================
// edge kernel: HMMA bf16-3split, 64 edges / CTA, 256 threads, 2 CTA/SM,
//   3-buffer ring, ONE sync per subchunk, CP issued right after sync.
// ======================================================================
__global__ __launch_bounds__(256, 2)
void edge_mma_kernel(const float* __restrict__ x,
                     const void* __restrict__ edge_index,
                     const float* __restrict__ edge_attr,
                     const float* __restrict__ b1a, const float* __restrict__ b1b,
                     int E, int N)
{
    extern __shared__ __align__(16) unsigned char smem[];
    const uint32_t sbase = smem_u32(smem);
    const int tid  = threadIdx.x;
    const int lane = tid & 31;
    const int w    = tid >> 5;
    const int g    = lane >> 2;
    const int tg   = lane & 3;
    const int mb   = (w >> 2) * 32;
    const int nb   = (w & 3) * 64;
    const int sel  = lane >> 3;
    const int rin  = lane & 7;

    const int e0 = blockIdx.x * 64;
    const int ecnt = min(64, E - e0);
    int*   srow = (int*)(smem + SROW);
    int*   scol = (int*)(smem + SCOL);
    float* sba  = (float*)(smem + SBIA);
    float* sbb  = (float*)(smem + SBIB);

    if (tid < 64) {
        int r = -1, c = -1;
        if (tid < ecnt) {
            r = load_idx(edge_index, (long long)(e0 + tid), N);
            c = load_idx(edge_index, (long long)E + e0 + tid, N);
            atomicAdd(&g_cnt[c], 1);
        }
        srow[tid] = r;
        scol[tid] = c;
    }
    if (tid < 256) {
        sba[tid] = b1a[tid];
        sbb[tid] = b1b[tid];
    }
    __syncthreads();

    // ---- gather inputs, split, store to A_hi/A_lo ----
    for (int idx = tid; idx < 64 * 32; idx += 256) {
        int e = idx >> 5, c4 = idx & 31;
        float4 v = make_float4(0.f, 0.f, 0.f, 0.f);
        if (e < ecnt) v = *(const float4*)(x + (long long)srow[e] * 128 + c4 * 4);
        uint32_t h0, l0, h1, l1;
        split2(v.x, v.y, h0, l0);
        split2(v.z, v.w, h1, l1);
        uint32_t off = (uint32_t)e * A_STRIDE_B + (uint32_t)c4 * 8;
        *(uint2*)(smem + SA_HI + off) = make_uint2(h0, h1);
        *(uint2*)(smem + SA_LO + off) = make_uint2(l0, l1);
    }
    for (int idx = tid; idx < 64 * 32; idx += 256) {
        int e = idx >> 5, c4 = idx & 31;
        float4 v = make_float4(0.f, 0.f, 0.f, 0.f);
        if (e < ecnt) v = *(const float4*)(edge_attr + (long long)(e0 + e) * 128 + c4 * 4);
        uint32_t h0, l0, h1, l1;
        split2(v.x, v.y, h0, l0);
        split2(v.z, v.w, h1, l1);
        uint32_t off = (uint32_t)e * A_STRIDE_B + 256u + (uint32_t)c4 * 8;
        *(uint2*)(smem + SA_HI + off) = make_uint2(h0, h1);
        *(uint2*)(smem + SA_LO + off) = make_uint2(l0, l1);
    }
    __syncthreads();

    float acc[2][8][4];
    #pragma unroll
    for (int mt = 0; mt < 2; mt++)
        #pragma unroll
        for (int nt = 0; nt < 8; nt++)
            #pragma unroll
            for (int i = 0; i < 4; i++) acc[mt][nt][i] = 0.f;

    uint32_t ahi[2][4], alo[2][4];

    // subchunk source: 0..31 -> w1a, 32..63 -> w1b
    #define SRC(S) ((S) < 32 ? g_w1blob + (S) * SUB_BYTES : g_w2blob + ((S) - 32) * SUB_BYTES)

    // prologue: prefetch subchunks 0 and 1 into ring slots 0, 1
    CP_SUB(SRC(0), SBUF0 + 0 * SUB_BYTES);
    CP_COMMIT();
    CP_SUB(SRC(1), SBUF0 + 1 * SUB_BYTES);
    CP_COMMIT();

    int bufc = 0;                   // ring slot holding subchunk s
    int bufn = 2;                   // ring slot for subchunk s+2
    // ---- unified mainloop: 64 subchunks, one sync each, early CP ----
    for (int s = 0; s < 64; s++) {
        CP_WAIT1();                 // group s complete (<=1 outstanding after)
        __syncthreads();            // visibility + all iter s-1 readers done
        if (s + 2 < 64) { CP_SUB(SRC(s + 2), SBUF0 + (uint32_t)bufn * SUB_BYTES); }
        CP_COMMIT();                // uniform group accounting
        uint32_t sb = SBUF0 + (uint32_t)bufc * SUB_BYTES;
        int sl = s & 31;
        if (!(sl & 1)) { A_LOAD(SA_HI, SA_LO, A_STRIDE_B, sl >> 1); B_PASS(sb, 2); }
        else           { B_PASS(sb, 1); }

        if (s == 31) {
            // ---- layer-1 epilogue: bias + ELU + re-split -> overwrite A ----
            __syncthreads();        // all GEMM1 A-reads done before rewrite
            #pragma unroll
            for (int mt = 0; mt < 2; mt++) {
                uint32_t r0 = (uint32_t)(mb + mt * 16 + g);
                #pragma unroll
                for (int nt = 0; nt < 8; nt++) {
                    int cb = nb + nt * 8 + tg * 2;
                    float b0 = sba[cb], b1 = sba[cb + 1];
                    float v00 = acc[mt][nt][0] + b0, v01 = acc[mt][nt][1] + b1;
                    float v10 = acc[mt][nt][2] + b0, v11 = acc[mt][nt][3] + b1;
                    v00 = (v00 > 0.f) ? v00 : expm1f(v00);
                    v01 = (v01 > 0.f) ? v01 : expm1f(v01);
                    v10 = (v10 > 0.f) ? v10 : expm1f(v10);
                    v11 = (v11 > 0.f) ? v11 : expm1f(v11);
                    uint32_t hi, lo;
                    uint32_t o = r0 * A_STRIDE_B + (uint32_t)cb * 2;
                    split2(v00, v01, hi, lo);
                    *(uint32_t*)(smem + SA_HI + o) = hi;
                    *(uint32_t*)(smem + SA_LO + o) = lo;
                    o += 8 * A_STRIDE_B;
                    split2(v10, v11, hi, lo);
                    *(uint32_t*)(smem + SA_HI + o) = hi;
                    *(uint32_t*)(smem + SA_LO + o) = lo;
                    acc[mt][nt][0] = 0.f; acc[mt][nt][1] = 0.f;
                    acc[mt][nt][2] = 0.f; acc[mt][nt][3] = 0.f;
                }
            }
            // new A visible to all at top sync of iter 32
        }
        bufc = (bufc == 2) ? 0 : bufc + 1;
        bufn = (bufn == 2) ? 0 : bufn + 1;
    }
    #undef SRC

    // ---- scatter epilogue: + b1b, red.global.add.v2 into g_sums ----
    {
        #pragma unroll
        for (int mt = 0; mt < 2; mt++) {
            int er0 = mb + mt * 16 + g;
            int c0 = scol[er0];
            int c1 = scol[er0 + 8];
            float* p0 = (c0 >= 0) ? (g_sums + (long long)c0 * 256) : nullptr;
            float* p1 = (c1 >= 0) ? (g_sums + (long long)c1 * 256) : nullptr;
            #pragma unroll
            for (int nt = 0; nt < 8; nt++) {
                int cb = nb + nt * 8 + tg * 2;
                float b0 = sbb[cb], b1 = sbb[cb + 1];
                if (p0) red_add_v2(p0 + cb, acc[mt][nt][0] + b0, acc[mt][nt][1] + b1);
                if (p1) red_add_v2(p1 + cb, acc[mt][nt][2] + b0, acc[mt][nt][3] + b1);
            }
        }
    }
}

// ======================================================================
// node kernel: HMMA bf16-3split, 64 nodes / CTA, 256 threads,
//   unified 80-subchunk stream, same 1-sync ring.
// ======================================================================
__global__ __launch_bounds__(256, 1)
void node_mma_kernel(const float* __restrict__ x,
                     const float* __restrict__ b2a, const float* __restrict__ b2b,
                     float* __restrict__ out, int N)
{
    extern __shared__ __align__(16) unsigned char smem[];
    const uint32_t sbase = smem_u32(smem);
    const int tid  = threadIdx.x;
    const int lane = tid & 31;
    const int w    = tid >> 5;
    const int g    = lane >> 2;
    const int tg   = lane & 3;
    const int mb   = (w >> 2) * 32;
    const int nb   = (w & 3) * 64;
    const int sel  = lane >> 3;
    const int rin  = lane & 7;

    const int n0 = blockIdx.x * 64;
    const int ncnt = min(64, N - n0);
    float* sba  = (float*)(smem + NB2A);
    float* sbb  = (float*)(smem + NB2B);
    float* sinv = (float*)(smem + NSINV);

    if (tid < 64) {
        float inv = 0.f;
        if (tid < ncnt) inv = 1.0f / (float)max(g_cnt[n0 + tid], 1);
        sinv[tid] = inv;
    }
    if (tid < 256) {
        sba[tid] = b2a[tid];
        sbb[tid] = b2b[tid];
    }
    __syncthreads();

    for (int idx = tid; idx < 64 * 32; idx += 256) {
        int e = idx >> 5, c4 = idx & 31;
        float4 v = make_float4(0.f, 0.f, 0.f, 0.f);
        if (e < ncnt) v = *(const float4*)(x + (long long)(n0 + e) * 128 + c4 * 4);
        uint32_t h0, l0, h1, l1;
        split2(v.x, v.y, h0, l0);
        split2(v.z, v.w, h1, l1);
        uint32_t off = (uint32_t)e * NA_STRIDE_B + (uint32_t)c4 * 8;
        *(uint2*)(smem + NA_HI + off) = make_uint2(h0, h1);
        *(uint2*)(smem + NA_LO + off) = make_uint2(l0, l1);
    }
    for (int idx = tid; idx < 64 * 64; idx += 256) {
        int e = idx >> 6, c4 = idx & 63;
        float4 v = make_float4(0.f, 0.f, 0.f, 0.f);
        if (e < ncnt) {
            v = *(const float4*)(g_sums + (long long)(n0 + e) * 256 + c4 * 4);
            float inv = sinv[e];
            v.x *= inv; v.y *= inv; v.z *= inv; v.w *= inv;
        }
        uint32_t h0, l0, h1, l1;
        split2(v.x, v.y, h0, l0);
        split2(v.z, v.w, h1, l1);
        uint32_t off = (uint32_t)e * NA_STRIDE_B + 256u + (uint32_t)c4 * 8;
        *(uint2*)(smem + NA_HI + off) = make_uint2(h0, h1);
        *(uint2*)(smem + NA_LO + off) = make_uint2(l0, l1);
    }
    __syncthreads();

    float acc[2][8][4];
    #pragma unroll
    for (int mt = 0; mt < 2; mt++)
        #pragma unroll
        for (int nt = 0; nt < 8; nt++)
            #pragma unroll
            for (int i = 0; i < 4; i++) acc[mt][nt][i] = 0.f;

    uint32_t ahi[2][4], alo[2][4];

    // subchunk source: 0..47 -> w2a, 48..79 -> w2b
    #define SRCN(S) ((S) < 48 ? g_wnablob + (S) * SUB_BYTES : g_wnbblob + ((S) - 48) * SUB_BYTES)

    CP_SUB(SRCN(0), NBUF0 + 0 * SUB_BYTES);
    CP_COMMIT();
    CP_SUB(SRCN(1), NBUF0 + 1 * SUB_BYTES);
    CP_COMMIT();

    int bufc = 0, bufn = 2;
    for (int s = 0; s < 80; s++) {
        CP_WAIT1();
        __syncthreads();
        if (s + 2 < 80) { CP_SUB(SRCN(s + 2), NBUF0 + (uint32_t)bufn * SUB_BYTES); }
        CP_COMMIT();
        uint32_t sb = NBUF0 + (uint32_t)bufc * SUB_BYTES;
        int sl = (s < 48) ? s : (s - 48);
        if (!(sl & 1)) { A_LOAD(NA_HI, NA_LO, NA_STRIDE_B, sl >> 1); B_PASS(sb, 2); }
        else           { B_PASS(sb, 1); }

        if (s == 47) {
            // ---- layer epilogue: bias + ELU + re-split -> overwrite NA ----
            __syncthreads();
            #pragma unroll
            for (int mt = 0; mt < 2; mt++) {
                uint32_t r0 = (uint32_t)(mb + mt * 16 + g);
                #pragma unroll
                for (int nt = 0; nt < 8; nt++) {
                    int cb = nb + nt * 8 + tg * 2;
                    float b0 = sba[cb], b1 = sba[cb + 1];
                    float v00 = acc[mt][nt][0] + b0, v01 = acc[mt][nt][1] + b1;
                    float v10 = acc[mt][nt][2] + b0, v11 = acc[mt][nt][3] + b1;
                    v00 = (v00 > 0.f) ? v00 : expm1f(v00);
                    v01 = (v01 > 0.f) ? v01 : expm1f(v01);
                    v10 = (v10 > 0.f) ? v10 : expm1f(v10);
                    v11 = (v11 > 0.f) ? v11 : expm1f(v11);
                    uint32_t hi, lo;
                    uint32_t o = r0 * NA_STRIDE_B + (uint32_t)cb * 2;
                    split2(v00, v01, hi, lo);
                    *(uint32_t*)(smem + NA_HI + o) = hi;
                    *(uint32_t*)(smem + NA_LO + o) = lo;
                    o += 8 * NA_STRIDE_B;
                    split2(v10, v11, hi, lo);
                    *(uint32_t*)(smem + NA_HI + o) = hi;
                    *(uint32_t*)(smem + NA_LO + o) = lo;
                    acc[mt][nt][0] = 0.f; acc[mt][nt][1] = 0.f;
                    acc[mt][nt][2] = 0.f; acc[mt][nt][3] = 0.f;
                }
            }
        }
        bufc = (bufc == 2) ? 0 : bufc + 1;
        bufn = (bufn == 2) ? 0 : bufn + 1;
    }
    #undef SRCN

    // ---- final epilogue: + b2b -> out ----
    {
        #pragma unroll
        for (int mt = 0; mt < 2; mt++) {
            int r0 = mb + mt * 16 + g;
            int nrow0 = n0 + r0, nrow1 = n0 + r0 + 8;
            #pragma unroll
            for (int nt = 0; nt < 8; nt++) {
                int cb = nb + nt * 8 + tg * 2;
                float b0 = sbb[cb], b1 = sbb[cb + 1];
                if (r0 < ncnt)
                    *(float2*)(out + (long long)nrow0 * 256 + cb) =
                        make_float2(acc[mt][nt][0] + b0, acc[mt][nt][1] + b1);
                if (r0 + 8 < ncnt)
                    *(float2*)(out + (long long)nrow1 * 256 + cb) =
                        make_float2(acc[mt][nt][2] + b0, acc[mt][nt][3] + b1);
            }
        }
    }
}

// ======================================================================
// launch
// ======================================================================
extern "C" void kernel_launch(void* const* d_in, const int* in_sizes, int n_in,
                              void* d_out, int out_size)
{
    const float* x  = (const float*)d_in[0];
    const void*  ei = d_in[1];
    const float* ea = (const float*)d_in[2];
    const float* w1a = (const float*)d_in[5];
    const float* b1a = (const float*)d_in[6];
    const float* w1b = (const float*)d_in[7];
    const float* b1b = (const float*)d_in[8];
    const float* w2a = (const float*)d_in[9];
    const float* b2a = (const float*)d_in[10];
    const float* w2b = (const float*)d_in[11];
    const float* b2b = (const float*)d_in[12];
    float* out = (float*)d_out;

    const int N = in_sizes[0] / 128;
    const int E = in_sizes[1] / 2;

    unsigned char *w1blob = nullptr, *w2blob = nullptr, *wnablob = nullptr, *wnbblob = nullptr;
    cudaGetSymbolAddress((void**)&w1blob, g_w1blob);
    cudaGetSymbolAddress((void**)&w2blob, g_w2blob);
    cudaGetSymbolAddress((void**)&wnablob, g_wnablob);
    cudaGetSymbolAddress((void**)&wnbblob, g_wnbblob);

    cudaFuncSetAttribute(edge_mma_kernel, cudaFuncAttributeMaxDynamicSharedMemorySize, EDGE_SMEM);
    cudaFuncSetAttribute(node_mma_kernel, cudaFuncAttributeMaxDynamicSharedMemorySize, NODE_SMEM);

    zero_detect_kernel<<<1024, 256>>>((const int*)ei, N);
    prep_weights_kernel<<<128, 512>>>(w1a, w1blob, 256);
    prep_weights_kernel<<<128, 512>>>(w1b, w2blob, 256);
    prep_weights_kernel<<<192, 512>>>(w2a, wnablob, 384);
    prep_weights_kernel<<<128, 512>>>(w2b, wnbblob, 256);
    edge_mma_kernel<<<(E + 63) / 64, 256, EDGE_SMEM>>>(x, ei, ea, b1a, b1b, E, N);
    node_mma_kernel<<<(N + 63) / 64, 256, NODE_SMEM>>>(x, b2a, b2b, out, N);
}

// round 16
// speedup vs baseline: 1.1637x; 1.0568x over previous
#include <cuda_runtime.h>
#include <cuda_bf16.h>
#include <cstdint>

// ---------------- problem constants ----------------
#define MAXN 50000

// ---------------- device scratch ----------------
__device__ float g_sums[MAXN * 256];
__device__ int   g_cnt [MAXN];
__device__ int   g_idx64;
// weight blobs: subchunk = one k16 slice, [n (256)][stride 48 B], hi then lo
#define SUB_BYTES 12288
__device__ __align__(16) unsigned char g_w1blob[32 * SUB_BYTES];   // w1a (K=256)
__device__ __align__(16) unsigned char g_w2blob[32 * SUB_BYTES];   // w1b (K=256)
__device__ __align__(16) unsigned char g_wnablob[48 * SUB_BYTES];  // w2a (K=384)
__device__ __align__(16) unsigned char g_wnbblob[32 * SUB_BYTES];  // w2b (K=256)

// ---------------- edge smem layout (bytes) ----------------
#define A_STRIDE_B 528              // 264 halves per row (256 + 8 pad)
#define SA_HI  0                    // 64*528 = 33792
#define SA_LO  33792
#define SB0    67584
#define SB1    79872
#define SBIA   92160
#define SBIB   93184
#define SROW   94208
#define SCOL   94464
#define EDGE_SMEM 94720

// ---------------- node smem layout (bytes) ----------------
#define NA_STRIDE_B 784             // 392 halves per row (384 + 8 pad)
#define NA_HI  0
#define NA_LO  50176
#define NB0    100352
#define NB1    112640
#define NB2A   124928
#define NB2B   125952
#define NSINV  126976
#define NODE_SMEM 127232

// ---------------- helpers ----------------
__device__ __forceinline__ uint32_t smem_u32(const void* p) {
    uint32_t a;
    asm("{ .reg .u64 t; cvta.to.shared.u64 t, %1; cvt.u32.u64 %0, t; }" : "=r"(a) : "l"(p));
    return a;
}
__device__ __forceinline__ void cp16(uint32_t saddr, const void* gaddr) {
    asm volatile("cp.async.cg.shared.global [%0], [%1], 16;" :: "r"(saddr), "l"(gaddr));
}
#define CP_COMMIT() asm volatile("cp.async.commit_group;")
#define CP_WAIT1()  asm volatile("cp.async.wait_group 1;")

__device__ __forceinline__ void red_add_v2(float* p, float a, float b) {
    asm volatile("red.global.add.v2.f32 [%0], {%1, %2};" :: "l"(p), "f"(a), "f"(b) : "memory");
}
__device__ __forceinline__ void mma16816(float* c, const uint32_t* a, const uint32_t* b) {
    asm volatile(
        "mma.sync.aligned.m16n8k16.row.col.f32.bf16.bf16.f32 "
        "{%0,%1,%2,%3}, {%4,%5,%6,%7}, {%8,%9}, {%0,%1,%2,%3};"
        : "+f"(c[0]), "+f"(c[1]), "+f"(c[2]), "+f"(c[3])
        : "r"(a[0]), "r"(a[1]), "r"(a[2]), "r"(a[3]), "r"(b[0]), "r"(b[1]));
}
__device__ __forceinline__ void ldm_x4(uint32_t addr, uint32_t* r) {
    asm volatile("ldmatrix.sync.aligned.m8n8.x4.shared.b16 {%0,%1,%2,%3}, [%4];"
                 : "=r"(r[0]), "=r"(r[1]), "=r"(r[2]), "=r"(r[3]) : "r"(addr));
}
__device__ __forceinline__ void split2(float v0, float v1, uint32_t& hi, uint32_t& lo) {
    __nv_bfloat16 h0 = __float2bfloat16(v0), h1 = __float2bfloat16(v1);
    __nv_bfloat162 hh{h0, h1};
    __nv_bfloat162 ll{__float2bfloat16(v0 - __bfloat162float(h0)),
                      __float2bfloat16(v1 - __bfloat162float(h1))};
    hi = *(uint32_t*)&hh;
    lo = *(uint32_t*)&ll;
}

// ======================================================================
// detect index dtype
// ======================================================================
__global__ void detect_idx_kernel(const int* __restrict__ ei_raw) {
    __shared__ int any_nonzero;
    if (threadIdx.x == 0) any_nonzero = 0;
    __syncthreads();
    for (int i = threadIdx.x; i < 1024; i += blockDim.x)
        if (ei_raw[2 * i + 1] != 0) any_nonzero = 1;
    __syncthreads();
    if (threadIdx.x == 0) g_idx64 = (any_nonzero == 0) ? 1 : 0;
}
__device__ __forceinline__ int load_idx(const void* ei, long long pos, int nmax) {
    int v = g_idx64 ? (int)((const long long*)ei)[pos] : ((const int*)ei)[pos];
    return min(max(v, 0), nmax - 1);
}

// ======================================================================
// zero scratch
// ======================================================================
__global__ void zero_kernel(int n_nodes) {
    int tid = blockIdx.x * blockDim.x + threadIdx.x;
    int stride = gridDim.x * blockDim.x;
    int tot4 = n_nodes * 64;
    float4* s4 = (float4*)g_sums;
    float4 z = make_float4(0.f, 0.f, 0.f, 0.f);
    for (int i = tid; i < tot4; i += stride) s4[i] = z;
    for (int i = tid; i < n_nodes; i += stride) g_cnt[i] = 0;
}

// ======================================================================
// prep: w [K][256 N] fp32 -> subchunks (B^T, 48B padded rows)
//   sub 2*(k>>4) : hi at n*48 + (k&15)*2 ; sub 2*(k>>4)+1 : lo
// ======================================================================
__global__ void prep_weights_kernel(const float* __restrict__ w, unsigned char* __restrict__ blob, int K) {
    int idx = blockIdx.x * blockDim.x + threadIdx.x;
    if (idx >= K * 256) return;
    int k = idx >> 8, n = idx & 255;
    float v = w[idx];
    __nv_bfloat16 hi = __float2bfloat16(v);
    __nv_bfloat16 lo = __float2bfloat16(v - __bfloat162float(hi));
    unsigned char* base = blob + (uint32_t)(k >> 4) * (2 * SUB_BYTES) + n * 48 + (k & 15) * 2;
    *(__nv_bfloat16*)(base)             = hi;
    *(__nv_bfloat16*)(base + SUB_BYTES) = lo;
}

// ---- shared GEMM machinery macros ----
#define CP_SUB(GSRC, SDST)                                             \
    {                                                                  \
        const unsigned char* _g = (GSRC);                              \
        uint32_t _s = sbase + (SDST);                                  \
        _Pragma("unroll")                                              \
        for (int _j = 0; _j < 3; _j++)                                 \
            cp16(_s + (tid + _j * 256) * 16, _g + (tid + _j * 256) * 16); \
    }

#define A_LOAD(SAHI, SALO, STRIDE, C)                                  \
    _Pragma("unroll")                                                  \
    for (int mt = 0; mt < 2; mt++) {                                   \
        uint32_t row = (uint32_t)(mb + mt * 16 + ((sel & 1) << 3) + rin); \
        uint32_t byt = row * (STRIDE) + (uint32_t)(C) * 32 + ((sel >> 1) << 4); \
        ldm_x4(sbase + (SAHI) + byt, ahi[mt]);                         \
        ldm_x4(sbase + (SALO) + byt, alo[mt]);                         \
    }

#define B_PASS(SBCUR, NTERMS)                                          \
    _Pragma("unroll")                                                  \
    for (int j = 0; j < 8; j += 2) {                                   \
        uint32_t n = (uint32_t)(nb + (j + (sel >> 1)) * 8 + rin);      \
        uint32_t byt = n * 48u + ((uint32_t)(sel & 1) << 4);           \
        uint32_t b[4];                                                 \
        ldm_x4(sbase + (SBCUR) + byt, b);                              \
        _Pragma("unroll")                                              \
        for (int mt = 0; mt < 2; mt++) {                               \
            mma16816(acc[mt][j],     ahi[mt], b);                      \
            mma16816(acc[mt][j + 1], ahi[mt], b + 2);                  \
            if (NTERMS == 2) {                                         \
                mma16816(acc[mt][j],     alo[mt], b);                  \
                mma16816(acc[mt][j + 1], alo[mt], b + 2);              \
            }                                                          \
        }                                                              \
    }

// ======================================================================
// edge kernel: HMMA bf16-3split, 64 edges / CTA, 256 threads, 2 CTA/SM
// ======================================================================
__global__ __launch_bounds__(256, 2)
void edge_mma_kernel(const float* __restrict__ x,
                     const void* __restrict__ edge_index,
                     const float* __restrict__ edge_attr,
                     const float* __restrict__ b1a, const float* __restrict__ b1b,
                     int E, int N)
{
    extern __shared__ __align__(16) unsigned char smem[];
    const uint32_t sbase = smem_u32(smem);
    const int tid  = threadIdx.x;
    const int lane = tid & 31;
    const int w    = tid >> 5;
    const int g    = lane >> 2;
    const int tg   = lane & 3;
    const int mb   = (w >> 2) * 32;
    const int nb   = (w & 3) * 64;
    const int sel  = lane >> 3;
    const int rin  = lane & 7;

    const int e0 = blockIdx.x * 64;
    const int ecnt = min(64, E - e0);
    int*   srow = (int*)(smem + SROW);
    int*   scol = (int*)(smem + SCOL);
    float* sba  = (float*)(smem + SBIA);
    float* sbb  = (float*)(smem + SBIB);

    if (tid < 64) {
        int r = -1, c = -1;
        if (tid < ecnt) {
            r = load_idx(edge_index, (long long)(e0 + tid), N);
            c = load_idx(edge_index, (long long)E + e0 + tid, N);
            atomicAdd(&g_cnt[c], 1);
        }
        srow[tid] = r;
        scol[tid] = c;
    }
    if (tid < 256) {
        sba[tid] = b1a[tid];
        sbb[tid] = b1b[tid];
    }
    __syncthreads();

    for (int idx = tid; idx < 64 * 32; idx += 256) {
        int e = idx >> 5, c4 = idx & 31;
        float4 v = make_float4(0.f, 0.f, 0.f, 0.f);
        if (e < ecnt) v = *(const float4*)(x + (long long)srow[e] * 128 + c4 * 4);
        uint32_t h0, l0, h1, l1;
        split2(v.x, v.y, h0, l0);
        split2(v.z, v.w, h1, l1);
        uint32_t off = (uint32_t)e * A_STRIDE_B + (uint32_t)c4 * 8;
        *(uint2*)(smem + SA_HI + off) = make_uint2(h0, h1);
        *(uint2*)(smem + SA_LO + off) = make_uint2(l0, l1);
    }
    for (int idx = tid; idx < 64 * 32; idx += 256) {
        int e = idx >> 5, c4 = idx & 31;
        float4 v = make_float4(0.f, 0.f, 0.f, 0.f);
        if (e < ecnt) v = *(const float4*)(edge_attr + (long long)(e0 + e) * 128 + c4 * 4);
        uint32_t h0, l0, h1, l1;
        split2(v.x, v.y, h0, l0);
        split2(v.z, v.w, h1, l1);
        uint32_t off = (uint32_t)e * A_STRIDE_B + 256u + (uint32_t)c4 * 8;
        *(uint2*)(smem + SA_HI + off) = make_uint2(h0, h1);
        *(uint2*)(smem + SA_LO + off) = make_uint2(l0, l1);
    }
    __syncthreads();

    float acc[2][8][4];
    #pragma unroll
    for (int mt = 0; mt < 2; mt++)
        #pragma unroll
        for (int nt = 0; nt < 8; nt++)
            #pragma unroll
            for (int i = 0; i < 4; i++) acc[mt][nt][i] = 0.f;

    uint32_t ahi[2][4], alo[2][4];

    // ---- GEMM1 ----
    CP_SUB(g_w1blob, SB0);
    CP_COMMIT();
    for (int s = 0; s < 32; s++) {
        if (s < 31) { CP_SUB(g_w1blob + (s + 1) * SUB_BYTES, ((s + 1) & 1) ? SB1 : SB0); }
        else        { CP_SUB(g_w2blob, SB0); }
        CP_COMMIT();
        CP_WAIT1();
        __syncthreads();
        uint32_t sb = (s & 1) ? SB1 : SB0;
        if (!(s & 1)) { A_LOAD(SA_HI, SA_LO, A_STRIDE_B, s >> 1); B_PASS(sb, 2); }
        else          { B_PASS(sb, 1); }
        __syncthreads();
    }

    // ---- layer-1 epilogue ----
    {
        #pragma unroll
        for (int mt = 0; mt < 2; mt++) {
            uint32_t r0 = (uint32_t)(mb + mt * 16 + g);
            #pragma unroll
            for (int nt = 0; nt < 8; nt++) {
                int cb = nb + nt * 8 + tg * 2;
                float b0 = sba[cb], b1 = sba[cb + 1];
                float v00 = acc[mt][nt][0] + b0, v01 = acc[mt][nt][1] + b1;
                float v10 = acc[mt][nt][2] + b0, v11 = acc[mt][nt][3] + b1;
                v00 = (v00 > 0.f) ? v00 : expm1f(v00);
                v01 = (v01 > 0.f) ? v01 : expm1f(v01);
                v10 = (v10 > 0.f) ? v10 : expm1f(v10);
                v11 = (v11 > 0.f) ? v11 : expm1f(v11);
                uint32_t hi, lo;
                uint32_t o = r0 * A_STRIDE_B + (uint32_t)cb * 2;
                split2(v00, v01, hi, lo);
                *(uint32_t*)(smem + SA_HI + o) = hi;
                *(uint32_t*)(smem + SA_LO + o) = lo;
                o += 8 * A_STRIDE_B;
                split2(v10, v11, hi, lo);
                *(uint32_t*)(smem + SA_HI + o) = hi;
                *(uint32_t*)(smem + SA_LO + o) = lo;
                acc[mt][nt][0] = 0.f; acc[mt][nt][1] = 0.f;
                acc[mt][nt][2] = 0.f; acc[mt][nt][3] = 0.f;
            }
        }
    }
    __syncthreads();

    // ---- GEMM2 ----
    for (int s = 0; s < 32; s++) {
        if (s < 31) { CP_SUB(g_w2blob + (s + 1) * SUB_BYTES, ((s + 1) & 1) ? SB1 : SB0); }
        CP_COMMIT();
        CP_WAIT1();
        __syncthreads();
        uint32_t sb = (s & 1) ? SB1 : SB0;
        if (!(s & 1)) { A_LOAD(SA_HI, SA_LO, A_STRIDE_B, s >> 1); B_PASS(sb, 2); }
        else          { B_PASS(sb, 1); }
        __syncthreads();
    }

    // ---- scatter epilogue ----
    {
        #pragma unroll
        for (int mt = 0; mt < 2; mt++) {
            int er0 = mb + mt * 16 + g;
            int c0 = scol[er0];
            int c1 = scol[er0 + 8];
            float* p0 = (c0 >= 0) ? (g_sums + (long long)c0 * 256) : nullptr;
            float* p1 = (c1 >= 0) ? (g_sums + (long long)c1 * 256) : nullptr;
            #pragma unroll
            for (int nt = 0; nt < 8; nt++) {
                int cb = nb + nt * 8 + tg * 2;
                float b0 = sbb[cb], b1 = sbb[cb + 1];
                if (p0) red_add_v2(p0 + cb, acc[mt][nt][0] + b0, acc[mt][nt][1] + b1);
                if (p1) red_add_v2(p1 + cb, acc[mt][nt][2] + b0, acc[mt][nt][3] + b1);
            }
        }
    }
}

// ======================================================================
// node kernel: HMMA bf16-3split, 64 nodes / CTA, 256 threads
// ======================================================================
__global__ __launch_bounds__(256, 1)
void node_mma_kernel(const float* __restrict__ x,
                     const float* __restrict__ b2a, const float* __restrict__ b2b,
                     float* __restrict__ out, int N)
{
    extern __shared__ __align__(16) unsigned char smem[];
    const uint32_t sbase = smem_u32(smem);
    const int tid  = threadIdx.x;
    const int lane = tid & 31;
    const int w    = tid >> 5;
    const int g    = lane >> 2;
    const int tg   = lane & 3;
    const int mb   = (w >> 2) * 32;
    const int nb   = (w & 3) * 64;
    const int sel  = lane >> 3;
    const int rin  = lane & 7;

    const int n0 = blockIdx.x * 64;
    const int ncnt = min(64, N - n0);
    float* sba  = (float*)(smem + NB2A);
    float* sbb  = (float*)(smem + NB2B);
    float* sinv = (float*)(smem + NSINV);

    if (tid < 64) {
        float inv = 0.f;
        if (tid < ncnt) inv = 1.0f / (float)max(g_cnt[n0 + tid], 1);
        sinv[tid] = inv;
    }
    if (tid < 256) {
        sba[tid] = b2a[tid];
        sbb[tid] = b2b[tid];
    }
    __syncthreads();

    for (int idx = tid; idx < 64 * 32; idx += 256) {
        int e = idx >> 5, c4 = idx & 31;
        float4 v = make_float4(0.f, 0.f, 0.f, 0.f);
        if (e < ncnt) v = *(const float4*)(x + (long long)(n0 + e) * 128 + c4 * 4);
        uint32_t h0, l0, h1, l1;
        split2(v.x, v.y, h0, l0);
        split2(v.z, v.w, h1, l1);
        uint32_t off = (uint32_t)e * NA_STRIDE_B + (uint32_t)c4 * 8;
        *(uint2*)(smem + NA_HI + off) = make_uint2(h0, h1);
        *(uint2*)(smem + NA_LO + off) = make_uint2(l0, l1);
    }
    for (int idx = tid; idx < 64 * 64; idx += 256) {
        int e = idx >> 6, c4 = idx & 63;
        float4 v = make_float4(0.f, 0.f, 0.f, 0.f);
        if (e < ncnt) {
            v = *(const float4*)(g_sums + (long long)(n0 + e) * 256 + c4 * 4);
            float inv = sinv[e];
            v.x *= inv; v.y *= inv; v.z *= inv; v.w *= inv;
        }
        uint32_t h0, l0, h1, l1;
        split2(v.x, v.y, h0, l0);
        split2(v.z, v.w, h1, l1);
        uint32_t off = (uint32_t)e * NA_STRIDE_B + 256u + (uint32_t)c4 * 8;
        *(uint2*)(smem + NA_HI + off) = make_uint2(h0, h1);
        *(uint2*)(smem + NA_LO + off) = make_uint2(l0, l1);
    }
    __syncthreads();

    float acc[2][8][4];
    #pragma unroll
    for (int mt = 0; mt < 2; mt++)
        #pragma unroll
        for (int nt = 0; nt < 8; nt++)
            #pragma unroll
            for (int i = 0; i < 4; i++) acc[mt][nt][i] = 0.f;

    uint32_t ahi[2][4], alo[2][4];

    // ---- GEMM1: K=384 -> 48 subchunks ----
    CP_SUB(g_wnablob, NB0);
    CP_COMMIT();
    for (int s = 0; s < 48; s++) {
        if (s < 47) { CP_SUB(g_wnablob + (s + 1) * SUB_BYTES, ((s + 1) & 1) ? NB1 : NB0); }
        else        { CP_SUB(g_wnbblob, NB0); }
        CP_COMMIT();
        CP_WAIT1();
        __syncthreads();
        uint32_t sb = (s & 1) ? NB1 : NB0;
        if (!(s & 1)) { A_LOAD(NA_HI, NA_LO, NA_STRIDE_B, s >> 1); B_PASS(sb, 2); }
        else          { B_PASS(sb, 1); }
        __syncthreads();
    }

    // ---- layer epilogue ----
    {
        #pragma unroll
        for (int mt = 0; mt < 2; mt++) {
            uint32_t r0 = (uint32_t)(mb + mt * 16 + g);
            #pragma unroll
            for (int nt = 0; nt < 8; nt++) {
                int cb = nb + nt * 8 + tg * 2;
                float b0 = sba[cb], b1 = sba[cb + 1];
                float v00 = acc[mt][nt][0] + b0, v01 = acc[mt][nt][1] + b1;
                float v10 = acc[mt][nt][2] + b0, v11 = acc[mt][nt][3] + b1;
                v00 = (v00 > 0.f) ? v00 : expm1f(v00);
                v01 = (v01 > 0.f) ? v01 : expm1f(v01);
                v10 = (v10 > 0.f) ? v10 : expm1f(v10);
                v11 = (v11 > 0.f) ? v11 : expm1f(v11);
                uint32_t hi, lo;
                uint32_t o = r0 * NA_STRIDE_B + (uint32_t)cb * 2;
                split2(v00, v01, hi, lo);
                *(uint32_t*)(smem + NA_HI + o) = hi;
                *(uint32_t*)(smem + NA_LO + o) = lo;
                o += 8 * NA_STRIDE_B;
                split2(v10, v11, hi, lo);
                *(uint32_t*)(smem + NA_HI + o) = hi;
                *(uint32_t*)(smem + NA_LO + o) = lo;
                acc[mt][nt][0] = 0.f; acc[mt][nt][1] = 0.f;
                acc[mt][nt][2] = 0.f; acc[mt][nt][3] = 0.f;
            }
        }
    }
    __syncthreads();

    // ---- GEMM2: K=256 -> 32 subchunks ----
    for (int s = 0; s < 32; s++) {
        if (s < 31) { CP_SUB(g_wnbblob + (s + 1) * SUB_BYTES, ((s + 1) & 1) ? NB1 : NB0); }
        CP_COMMIT();
        CP_WAIT1();
        __syncthreads();
        uint32_t sb = (s & 1) ? NB1 : NB0;
        if (!(s & 1)) { A_LOAD(NA_HI, NA_LO, NA_STRIDE_B, s >> 1); B_PASS(sb, 2); }
        else          { B_PASS(sb, 1); }
        __syncthreads();
    }

    // ---- final epilogue: + b2b -> out ----
    {
        #pragma unroll
        for (int mt = 0; mt < 2; mt++) {
            int r0 = mb + mt * 16 + g;
            int nrow0 = n0 + r0, nrow1 = n0 + r0 + 8;
            #pragma unroll
            for (int nt = 0; nt < 8; nt++) {
                int cb = nb + nt * 8 + tg * 2;
                float b0 = sbb[cb], b1 = sbb[cb + 1];
                if (r0 < ncnt)
                    *(float2*)(out + (long long)nrow0 * 256 + cb) =
                        make_float2(acc[mt][nt][0] + b0, acc[mt][nt][1] + b1);
                if (r0 + 8 < ncnt)
                    *(float2*)(out + (long long)nrow1 * 256 + cb) =
                        make_float2(acc[mt][nt][2] + b0, acc[mt][nt][3] + b1);
            }
        }
    }
}

// ======================================================================
// launch
// ======================================================================
extern "C" void kernel_launch(void* const* d_in, const int* in_sizes, int n_in,
                              void* d_out, int out_size)
{
    const float* x  = (const float*)d_in[0];
    const void*  ei = d_in[1];
    const float* ea = (const float*)d_in[2];
    const float* w1a = (const float*)d_in[5];
    const float* b1a = (const float*)d_in[6];
    const float* w1b = (const float*)d_in[7];
    const float* b1b = (const float*)d_in[8];
    const float* w2a = (const float*)d_in[9];
    const float* b2a = (const float*)d_in[10];
    const float* w2b = (const float*)d_in[11];
    const float* b2b = (const float*)d_in[12];
    float* out = (float*)d_out;

    const int N = in_sizes[0] / 128;
    const int E = in_sizes[1] / 2;

    unsigned char *w1blob = nullptr, *w2blob = nullptr, *wnablob = nullptr, *wnbblob = nullptr;
    cudaGetSymbolAddress((void**)&w1blob, g_w1blob);
    cudaGetSymbolAddress((void**)&w2blob, g_w2blob);
    cudaGetSymbolAddress((void**)&wnablob, g_wnablob);
    cudaGetSymbolAddress((void**)&wnbblob, g_wnbblob);

    cudaFuncSetAttribute(edge_mma_kernel, cudaFuncAttributeMaxDynamicSharedMemorySize, EDGE_SMEM);
    cudaFuncSetAttribute(node_mma_kernel, cudaFuncAttributeMaxDynamicSharedMemorySize, NODE_SMEM);

    detect_idx_kernel<<<1, 256>>>((const int*)ei);
    zero_kernel<<<1024, 256>>>(N);
    prep_weights_kernel<<<128, 512>>>(w1a, w1blob, 256);
    prep_weights_kernel<<<128, 512>>>(w1b, w2blob, 256);
    prep_weights_kernel<<<192, 512>>>(w2a, wnablob, 384);
    prep_weights_kernel<<<128, 512>>>(w2b, wnbblob, 256);
    edge_mma_kernel<<<(E + 63) / 64, 256, EDGE_SMEM>>>(x, ei, ea, b1a, b1b, E, N);
    node_mma_kernel<<<(N + 63) / 64, 256, NODE_SMEM>>>(x, b2a, b2b, out, N);
}